// round 5
// baseline (speedup 1.0000x reference)
#include <cuda_runtime.h>
#include <cuda_bf16.h>

// Problem constants (fixed by reference setup_inputs)
#define B_SZ   4096
#define DIMK   512
#define MN_SZ  4096
#define GRID_N 64          // SOM grid is 64x64
#define NTILES 32          // MN_SZ / BN

// GEMM tiling
#define BM 128
#define BN 128
#define BK 16
#define PAD 4              // BM+PAD = 132 floats = 528B, multiple of 16 -> aligned float4

// Scratch (device globals; no allocation allowed)
__device__ float g_w2[MN_SZ];
__device__ float g_pval[B_SZ * NTILES];
__device__ int   g_pidx[B_SZ * NTILES];

// ---------------------------------------------------------------------------
// Kernel 1: w2[n] = sum_k weights[n][k]^2   (one warp per row)
// ---------------------------------------------------------------------------
__global__ void w2_kernel(const float* __restrict__ w) {
    int wid  = blockIdx.x * 8 + (threadIdx.x >> 5);
    int lane = threadIdx.x & 31;
    const float* row = w + (size_t)wid * DIMK;
    float s = 0.f;
    #pragma unroll
    for (int k = lane; k < DIMK; k += 32) { float v = row[k]; s += v * v; }
    #pragma unroll
    for (int o = 16; o > 0; o >>= 1) s += __shfl_down_sync(0xffffffffu, s, o);
    if (lane == 0) g_w2[wid] = s;
}

// ---------------------------------------------------------------------------
// Kernel 2: fused distance-GEMM + per-tile argmin.
// Block (bx,by): weights [bx*128, +128) x batch rows [by*128, +128), full K.
// d2 = w2[n] - 2*dot(batch[b], weights[n])   (x2 term constant per row)
// Writes per-row best (val, idx) over this 128-weight tile.
// ---------------------------------------------------------------------------
__global__ __launch_bounds__(256, 2)
void gemm_argmin_kernel(const float* __restrict__ A, const float* __restrict__ W) {
    __shared__ float As[BK][BM + PAD];
    __shared__ float Bs[BK][BN + PAD];
    __shared__ float red_v[BM][17];
    __shared__ int   red_i[BM][17];

    const int t  = threadIdx.x;
    const int tx = t & 15;
    const int ty = t >> 4;
    const int rowBase = blockIdx.y * BM;
    const int colBase = blockIdx.x * BN;

    float acc[8][8];
    #pragma unroll
    for (int i = 0; i < 8; i++)
        #pragma unroll
        for (int j = 0; j < 8; j++) acc[i][j] = 0.f;

    for (int k0 = 0; k0 < DIMK; k0 += BK) {
        // Load A tile (128 rows x 16 cols), store transposed As[k][m]
        #pragma unroll
        for (int u = 0; u < 2; u++) {
            int id = t * 2 + u;            // [0, 512) float4 ids
            int r  = id >> 2;
            int c4 = (id & 3) * 4;
            float4 v = *(const float4*)(A + (size_t)(rowBase + r) * DIMK + k0 + c4);
            As[c4 + 0][r] = v.x; As[c4 + 1][r] = v.y;
            As[c4 + 2][r] = v.z; As[c4 + 3][r] = v.w;
        }
        // Load W tile (128 weight rows x 16 cols), store transposed Bs[k][n]
        #pragma unroll
        for (int u = 0; u < 2; u++) {
            int id = t * 2 + u;
            int r  = id >> 2;
            int c4 = (id & 3) * 4;
            float4 v = *(const float4*)(W + (size_t)(colBase + r) * DIMK + k0 + c4);
            Bs[c4 + 0][r] = v.x; Bs[c4 + 1][r] = v.y;
            Bs[c4 + 2][r] = v.z; Bs[c4 + 3][r] = v.w;
        }
        __syncthreads();

        #pragma unroll
        for (int k = 0; k < BK; k++) {
            float a[8], b[8];
            float4 a0 = *(const float4*)&As[k][ty * 8];
            float4 a1 = *(const float4*)&As[k][ty * 8 + 4];
            float4 b0 = *(const float4*)&Bs[k][tx * 8];
            float4 b1 = *(const float4*)&Bs[k][tx * 8 + 4];
            a[0]=a0.x; a[1]=a0.y; a[2]=a0.z; a[3]=a0.w;
            a[4]=a1.x; a[5]=a1.y; a[6]=a1.z; a[7]=a1.w;
            b[0]=b0.x; b[1]=b0.y; b[2]=b0.z; b[3]=b0.w;
            b[4]=b1.x; b[5]=b1.y; b[6]=b1.z; b[7]=b1.w;
            #pragma unroll
            for (int i = 0; i < 8; i++)
                #pragma unroll
                for (int j = 0; j < 8; j++)
                    acc[i][j] += a[i] * b[j];
        }
        __syncthreads();
    }

    // Epilogue: per-thread argmin over its 8 columns for each of its 8 rows
    float w2l[8];
    #pragma unroll
    for (int j = 0; j < 8; j++) w2l[j] = g_w2[colBase + tx * 8 + j];

    #pragma unroll
    for (int i = 0; i < 8; i++) {
        float bv = w2l[0] - 2.f * acc[i][0];
        int   bi = colBase + tx * 8;
        #pragma unroll
        for (int j = 1; j < 8; j++) {
            float v = w2l[j] - 2.f * acc[i][j];
            if (v < bv) { bv = v; bi = colBase + tx * 8 + j; }   // ascending idx: strict <
        }
        red_v[ty * 8 + i][tx] = bv;
        red_i[ty * 8 + i][tx] = bi;
    }
    __syncthreads();

    if (t < BM) {
        float bv = red_v[t][0];
        int   bi = red_i[t][0];
        #pragma unroll
        for (int x = 1; x < 16; x++) {        // ascending tx -> ascending idx
            float v = red_v[t][x];
            int   i2 = red_i[t][x];
            if (v < bv || (v == bv && i2 < bi)) { bv = v; bi = i2; }
        }
        int row = rowBase + t;
        g_pval[row * NTILES + blockIdx.x] = bv;
        g_pidx[row * NTILES + blockIdx.x] = bi;
    }
}

// ---------------------------------------------------------------------------
// Kernel 3: one block per batch row.
//  - reduce 32 partial argmins -> BMU (i,j)
//  - separable Gaussian tables gx[64], gy[64] in smem (128 expf per block)
//  - stream 4096 floats out with float4 stores
// ---------------------------------------------------------------------------
__global__ void output_kernel(float* __restrict__ out,
                              const int* __restrict__ decay_p,
                              const int* __restrict__ it_p) {
    __shared__ float gx[GRID_N];
    __shared__ float gy[GRID_N];
    __shared__ int   s_bmu;

    const int b = blockIdx.x;
    const int t = threadIdx.x;

    if (t < 32) {
        float bv = g_pval[b * NTILES + t];
        int   bi = g_pidx[b * NTILES + t];
        #pragma unroll
        for (int o = 16; o > 0; o >>= 1) {
            float ov = __shfl_down_sync(0xffffffffu, bv, o);
            int   oi = __shfl_down_sync(0xffffffffu, bi, o);
            if (ov < bv || (ov == bv && oi < bi)) { bv = ov; bi = oi; }
        }
        if (t == 0) s_bmu = bi;
    }
    __syncthreads();

    const int bmu = s_bmu;
    const int bi  = bmu >> 6;      // location = (n / 64, n % 64)
    const int bj  = bmu & 63;

    // sigma_op = 32 * exp(-it/decay); read scalars from device (int32/int64-safe low word)
    const float itv = (float)it_p[0];
    const float dcv = (float)decay_p[0];
    const float lr  = __expf(-itv / dcv);
    const float sig = 32.0f * lr;
    const float inv = 1.0f / (sig * sig);

    if (t < GRID_N) {
        float d = (float)(t - bi);
        gx[t] = __expf(-d * d * inv);
    } else if (t < 2 * GRID_N) {
        int j = t - GRID_N;
        float d = (float)(j - bj);
        gy[j] = __expf(-d * d * inv);
    }
    __syncthreads();

    // 256 threads x 16 floats = 4096 per row
    const int i  = t >> 2;
    const int j0 = (t & 3) * 16;
    const float gxi = gx[i];
    float4* o4 = (float4*)(out + (size_t)b * MN_SZ + i * GRID_N + j0);
    #pragma unroll
    for (int q = 0; q < 4; q++) {
        float4 v;
        v.x = gxi * gy[j0 + 4 * q + 0];
        v.y = gxi * gy[j0 + 4 * q + 1];
        v.z = gxi * gy[j0 + 4 * q + 2];
        v.w = gxi * gy[j0 + 4 * q + 3];
        o4[q] = v;
    }
}

// ---------------------------------------------------------------------------
extern "C" void kernel_launch(void* const* d_in, const int* in_sizes, int n_in,
                              void* d_out, int out_size) {
    const float* batch   = (const float*)d_in[0];   // [4096, 512] f32
    const float* weights = (const float*)d_in[1];   // [4096, 512] f32
    // d_in[2] = locations (implicit grid, unused)
    const int* decay = (const int*)d_in[3];
    const int* it    = (const int*)d_in[4];
    float* out = (float*)d_out;

    w2_kernel<<<MN_SZ / 8, 256>>>(weights);         // 512 blocks x 8 warps = 4096 rows
    dim3 g(MN_SZ / BN, B_SZ / BM);                  // (32, 32)
    gemm_argmin_kernel<<<g, 256>>>(batch, weights);
    output_kernel<<<B_SZ, 256>>>(out, decay, it);
}

// round 8
// speedup vs baseline: 2.0266x; 2.0266x over previous
#include <cuda_runtime.h>
#include <cuda_bf16.h>
#include <cstdint>

// Problem constants
#define B_SZ   4096
#define DIMK   512
#define MN_SZ  4096
#define GRID_N 64
#define BM 128
#define BN 128
#define NTILES (MN_SZ / BN)        // 32 tiles -> 64 candidates/row
#define KITERS (DIMK / 32)         // 16

// smem geometry: 4 arrays (Ahi, Alo, Whi, Wlo), 128 rows x 32 bf16, stride 80B
#define STRIDE_B 80
#define ARR_SZ   (128 * STRIDE_B)   // 10240
#define STAGE_SZ (4 * ARR_SZ)       // 40960
#define SMEM_TOTAL (2 * STAGE_SZ)   // 81920

// ---- device scratch -------------------------------------------------------
__device__ float g_w2[MN_SZ];
__device__ __align__(16) __nv_bfloat16 g_Ahi[B_SZ * DIMK];
__device__ __align__(16) __nv_bfloat16 g_Alo[B_SZ * DIMK];
__device__ __align__(16) __nv_bfloat16 g_Whi[MN_SZ * DIMK];
__device__ __align__(16) __nv_bfloat16 g_Wlo[MN_SZ * DIMK];
__device__ float g_tv[B_SZ * NTILES * 2];
__device__ int   g_ti[B_SZ * NTILES * 2];

// ---- helpers --------------------------------------------------------------
__device__ __forceinline__ uint32_t smem_u32(const void* p) {
    uint32_t a;
    asm("{ .reg .u64 t; cvta.to.shared.u64 t, %1; cvt.u32.u64 %0, t; }" : "=r"(a) : "l"(p));
    return a;
}
__device__ __forceinline__ void cp16(uint32_t dst, const void* src) {
    asm volatile("cp.async.cg.shared.global [%0], [%1], 16;" :: "r"(dst), "l"(src));
}
#define CP_COMMIT() asm volatile("cp.async.commit_group;" ::: "memory")
#define CP_WAIT1()  asm volatile("cp.async.wait_group 1;" ::: "memory")

__device__ __forceinline__ void ldsm4(uint32_t* r, uint32_t a) {
    asm volatile("ldmatrix.sync.aligned.m8n8.x4.shared.b16 {%0,%1,%2,%3}, [%4];"
                 : "=r"(r[0]), "=r"(r[1]), "=r"(r[2]), "=r"(r[3]) : "r"(a));
}
__device__ __forceinline__ void mma16816(float* c, const uint32_t* a, const uint32_t* b) {
    asm volatile("mma.sync.aligned.m16n8k16.row.col.f32.bf16.bf16.f32 "
                 "{%0,%1,%2,%3}, {%4,%5,%6,%7}, {%8,%9}, {%0,%1,%2,%3};"
                 : "+f"(c[0]), "+f"(c[1]), "+f"(c[2]), "+f"(c[3])
                 : "r"(a[0]), "r"(a[1]), "r"(a[2]), "r"(a[3]), "r"(b[0]), "r"(b[1]));
}
__device__ __forceinline__ void merge2(float& v1, int& i1, float& v2, int& i2,
                                       float ov, int oi) {
    if (ov < v1 || (ov == v1 && oi < i1)) { v2 = v1; i2 = i1; v1 = ov; i1 = oi; }
    else if (ov < v2 || (ov == v2 && oi < i2)) { v2 = ov; i2 = oi; }
}

// ---------------------------------------------------------------------------
// Kernel 0: split fp32 -> bf16 hi/lo
// ---------------------------------------------------------------------------
__global__ void split_kernel(const float* __restrict__ a, const float* __restrict__ w) {
    int i = blockIdx.x * 256 + threadIdx.x;           // float4 index
    float4 x = ((const float4*)a)[i];
    float4 y = ((const float4*)w)[i];
    __nv_bfloat16 h0 = __float2bfloat16(x.x), h1 = __float2bfloat16(x.y);
    __nv_bfloat16 h2 = __float2bfloat16(x.z), h3 = __float2bfloat16(x.w);
    ((__nv_bfloat162*)g_Ahi)[i * 2 + 0] = __nv_bfloat162(h0, h1);
    ((__nv_bfloat162*)g_Ahi)[i * 2 + 1] = __nv_bfloat162(h2, h3);
    ((__nv_bfloat162*)g_Alo)[i * 2 + 0] = __nv_bfloat162(
        __float2bfloat16(x.x - __bfloat162float(h0)), __float2bfloat16(x.y - __bfloat162float(h1)));
    ((__nv_bfloat162*)g_Alo)[i * 2 + 1] = __nv_bfloat162(
        __float2bfloat16(x.z - __bfloat162float(h2)), __float2bfloat16(x.w - __bfloat162float(h3)));
    __nv_bfloat16 g0 = __float2bfloat16(y.x), g1 = __float2bfloat16(y.y);
    __nv_bfloat16 g2 = __float2bfloat16(y.z), g3 = __float2bfloat16(y.w);
    ((__nv_bfloat162*)g_Whi)[i * 2 + 0] = __nv_bfloat162(g0, g1);
    ((__nv_bfloat162*)g_Whi)[i * 2 + 1] = __nv_bfloat162(g2, g3);
    ((__nv_bfloat162*)g_Wlo)[i * 2 + 0] = __nv_bfloat162(
        __float2bfloat16(y.x - __bfloat162float(g0)), __float2bfloat16(y.y - __bfloat162float(g1)));
    ((__nv_bfloat162*)g_Wlo)[i * 2 + 1] = __nv_bfloat162(
        __float2bfloat16(y.z - __bfloat162float(g2)), __float2bfloat16(y.w - __bfloat162float(g3)));
}

// ---------------------------------------------------------------------------
// Kernel 1: w2[n] = ||weights[n]||^2 (fp32 exact)
// ---------------------------------------------------------------------------
__global__ void w2_kernel(const float* __restrict__ w) {
    int wid  = blockIdx.x * 8 + (threadIdx.x >> 5);
    int lane = threadIdx.x & 31;
    const float* row = w + (size_t)wid * DIMK;
    float s = 0.f;
    #pragma unroll
    for (int k = lane; k < DIMK; k += 32) { float v = row[k]; s += v * v; }
    #pragma unroll
    for (int o = 16; o > 0; o >>= 1) s += __shfl_down_sync(0xffffffffu, s, o);
    if (lane == 0) g_w2[wid] = s;
}

// ---------------------------------------------------------------------------
// Kernel 2: bf16x3 mma.sync GEMM (128x128 tile) + per-tile top-2
// ---------------------------------------------------------------------------
__device__ __forceinline__ void load_stage(uint32_t smBase, int buf, int kIter,
                                           int rowBase, int colBase, int t) {
    uint32_t stage = smBase + buf * STAGE_SZ;
    #pragma unroll
    for (int i = 0; i < 2; i++) {
        int cid = i * 256 + t;          // 512 16B-chunks per array
        int r = cid >> 2, c = cid & 3;
        uint32_t doff = (uint32_t)(r * STRIDE_B + c * 16);
        size_t gA = (size_t)(rowBase + r) * DIMK + kIter * 32 + c * 8;
        size_t gW = (size_t)(colBase + r) * DIMK + kIter * 32 + c * 8;
        cp16(stage + doff,              &g_Ahi[gA]);
        cp16(stage + ARR_SZ + doff,     &g_Alo[gA]);
        cp16(stage + 2 * ARR_SZ + doff, &g_Whi[gW]);
        cp16(stage + 3 * ARR_SZ + doff, &g_Wlo[gW]);
    }
}

__global__ void __launch_bounds__(256)
gemm_mma_kernel() {
    extern __shared__ char smem[];
    const uint32_t sm = smem_u32(smem);
    const int t    = threadIdx.x;
    const int wid  = t >> 5;
    const int lane = t & 31;
    const int warpM = (wid & 3) * 32;       // 4 warps over M
    const int warpN = (wid >> 2) * 64;      // 2 warps over N
    const int rowBase = blockIdx.y * BM;
    const int colBase = blockIdx.x * BN;

    float acc[2][8][4];
    #pragma unroll
    for (int a = 0; a < 2; a++)
        #pragma unroll
        for (int b = 0; b < 8; b++)
            #pragma unroll
            for (int q = 0; q < 4; q++) acc[a][b][q] = 0.f;

    load_stage(sm, 0, 0, rowBase, colBase, t); CP_COMMIT();
    load_stage(sm, 1, 1, rowBase, colBase, t); CP_COMMIT();

    for (int k = 0; k < KITERS; k++) {
        const int p = k & 1;
        CP_WAIT1();
        __syncthreads();

        const uint32_t aHi = sm + p * STAGE_SZ;
        const uint32_t bHi = aHi + 2 * ARR_SZ;

        #pragma unroll
        for (int ks = 0; ks < 2; ks++) {
            uint32_t ah[2][4], al[2][4];
            #pragma unroll
            for (int mf = 0; mf < 2; mf++) {
                uint32_t ao = (uint32_t)((warpM + mf * 16 + (lane & 15)) * STRIDE_B
                                         + ks * 32 + (lane >> 4) * 16);
                ldsm4(ah[mf], aHi + ao);
                ldsm4(al[mf], aHi + ARR_SZ + ao);
            }
            #pragma unroll
            for (int np = 0; np < 4; np++) {
                uint32_t bh[4], bl[4];
                int n = warpN + np * 16 + (lane & 7) + ((lane >> 4) & 1) * 8;
                uint32_t bo = (uint32_t)(n * STRIDE_B + ks * 32 + ((lane >> 3) & 1) * 16);
                ldsm4(bh, bHi + bo);
                ldsm4(bl, bHi + ARR_SZ + bo);
                #pragma unroll
                for (int mf = 0; mf < 2; mf++) {
                    #pragma unroll
                    for (int nn = 0; nn < 2; nn++) {
                        float* C = acc[mf][np * 2 + nn];
                        mma16816(C, ah[mf], &bh[nn * 2]);   // hi*hi
                        mma16816(C, ah[mf], &bl[nn * 2]);   // hi*lo
                        mma16816(C, al[mf], &bh[nn * 2]);   // lo*hi
                    }
                }
            }
        }
        __syncthreads();
        if (k + 2 < KITERS) load_stage(sm, p, k + 2, rowBase, colBase, t);
        CP_COMMIT();
    }

    // ---- epilogue: d2 = w2 - 2*dot, per-row top-2 within this 128-col tile
    __syncthreads();
    float* candV = (float*)smem;            // [128][4] (2 n-warps x 2)
    int*   candI = (int*)(smem + 2048);

    #pragma unroll
    for (int mf = 0; mf < 2; mf++) {
        #pragma unroll
        for (int half = 0; half < 2; half++) {
            float v1 = __int_as_float(0x7f800000), v2 = v1;
            int   i1 = 0x7fffffff,                i2 = i1;
            #pragma unroll
            for (int nf = 0; nf < 8; nf++) {
                #pragma unroll
                for (int q = 0; q < 2; q++) {
                    int col = colBase + warpN + nf * 8 + (lane & 3) * 2 + q;
                    float v = g_w2[col] - 2.f * acc[mf][nf][half * 2 + q];
                    merge2(v1, i1, v2, i2, v, col);
                }
            }
            // quad reduce (lanes sharing one row differ in lane&3)
            #pragma unroll
            for (int x = 1; x <= 2; x <<= 1) {
                float ov1 = __shfl_xor_sync(0xffffffffu, v1, x);
                int   oi1 = __shfl_xor_sync(0xffffffffu, i1, x);
                float ov2 = __shfl_xor_sync(0xffffffffu, v2, x);
                int   oi2 = __shfl_xor_sync(0xffffffffu, i2, x);
                merge2(v1, i1, v2, i2, ov1, oi1);
                merge2(v1, i1, v2, i2, ov2, oi2);
            }
            if ((lane & 3) == 0) {
                int rowL = warpM + mf * 16 + half * 8 + (lane >> 2);
                int nw   = wid >> 2;
                candV[rowL * 4 + nw * 2 + 0] = v1;
                candI[rowL * 4 + nw * 2 + 0] = i1;
                candV[rowL * 4 + nw * 2 + 1] = v2;
                candI[rowL * 4 + nw * 2 + 1] = i2;
            }
        }
    }
    __syncthreads();

    if (t < BM) {
        float v1 = candV[t * 4], v2 = __int_as_float(0x7f800000);
        int   i1 = candI[t * 4], i2 = 0x7fffffff;
        #pragma unroll
        for (int s = 1; s < 4; s++) merge2(v1, i1, v2, i2, candV[t * 4 + s], candI[t * 4 + s]);
        int row = rowBase + t;
        int o = row * (NTILES * 2) + blockIdx.x * 2;
        g_tv[o] = v1;     g_ti[o] = i1;
        g_tv[o + 1] = v2; g_ti[o + 1] = i2;
    }
}

// ---------------------------------------------------------------------------
// Kernel 3: reduce 64 candidates -> approx top-2 -> exact fp32 recheck ->
// BMU -> separable Gaussian output
// ---------------------------------------------------------------------------
__global__ void output_kernel(float* __restrict__ out,
                              const float* __restrict__ batch,
                              const float* __restrict__ weights,
                              const int* __restrict__ decay_p,
                              const int* __restrict__ it_p) {
    __shared__ float gx[GRID_N];
    __shared__ float gy[GRID_N];
    __shared__ int   s_bmu;

    const int b = blockIdx.x;
    const int t = threadIdx.x;

    if (t < 32) {
        float v1 = g_tv[b * 64 + t];
        int   i1 = g_ti[b * 64 + t];
        float v2 = g_tv[b * 64 + 32 + t];
        int   i2 = g_ti[b * 64 + 32 + t];
        if (v2 < v1 || (v2 == v1 && i2 < i1)) {
            float tv = v1; v1 = v2; v2 = tv;
            int   ti = i1; i1 = i2; i2 = ti;
        }
        #pragma unroll
        for (int o = 16; o > 0; o >>= 1) {
            float ov1 = __shfl_xor_sync(0xffffffffu, v1, o);
            int   oi1 = __shfl_xor_sync(0xffffffffu, i1, o);
            float ov2 = __shfl_xor_sync(0xffffffffu, v2, o);
            int   oi2 = __shfl_xor_sync(0xffffffffu, i2, o);
            merge2(v1, i1, v2, i2, ov1, oi1);
            merge2(v1, i1, v2, i2, ov2, oi2);
        }
        // exact fp32 recheck of the two candidates
        const float* br = batch + (size_t)b * DIMK;
        const float* w0 = weights + (size_t)i1 * DIMK;
        const float* w1 = weights + (size_t)i2 * DIMK;
        float s0 = 0.f, s1 = 0.f;
        #pragma unroll 4
        for (int k = t; k < DIMK; k += 32) {
            float x = br[k];
            s0 += x * w0[k];
            s1 += x * w1[k];
        }
        #pragma unroll
        for (int o = 16; o > 0; o >>= 1) {
            s0 += __shfl_down_sync(0xffffffffu, s0, o);
            s1 += __shfl_down_sync(0xffffffffu, s1, o);
        }
        if (t == 0) {
            float d0 = g_w2[i1] - 2.f * s0;
            float d1 = g_w2[i2] - 2.f * s1;
            s_bmu = (d1 < d0 || (d1 == d0 && i2 < i1)) ? i2 : i1;
        }
    }
    __syncthreads();

    const int bmu = s_bmu;
    const int bi  = bmu >> 6;
    const int bj  = bmu & 63;

    const float itv = (float)it_p[0];
    const float dcv = (float)decay_p[0];
    const float lr  = __expf(-itv / dcv);
    const float sig = 32.0f * lr;
    const float inv = 1.0f / (sig * sig);

    if (t < GRID_N) {
        float d = (float)(t - bi);
        gx[t] = __expf(-d * d * inv);
    } else if (t < 2 * GRID_N) {
        int j = t - GRID_N;
        float d = (float)(j - bj);
        gy[j] = __expf(-d * d * inv);
    }
    __syncthreads();

    const int i  = t >> 2;
    const int j0 = (t & 3) * 16;
    const float gxi = gx[i];
    float4* o4 = (float4*)(out + (size_t)b * MN_SZ + i * GRID_N + j0);
    #pragma unroll
    for (int q = 0; q < 4; q++) {
        float4 v;
        v.x = gxi * gy[j0 + 4 * q + 0];
        v.y = gxi * gy[j0 + 4 * q + 1];
        v.z = gxi * gy[j0 + 4 * q + 2];
        v.w = gxi * gy[j0 + 4 * q + 3];
        o4[q] = v;
    }
}

// ---------------------------------------------------------------------------
extern "C" void kernel_launch(void* const* d_in, const int* in_sizes, int n_in,
                              void* d_out, int out_size) {
    const float* batch   = (const float*)d_in[0];
    const float* weights = (const float*)d_in[1];
    const int* decay = (const int*)d_in[3];
    const int* it    = (const int*)d_in[4];
    float* out = (float*)d_out;

    cudaFuncSetAttribute(gemm_mma_kernel, cudaFuncAttributeMaxDynamicSharedMemorySize, SMEM_TOTAL);

    split_kernel<<<B_SZ * DIMK / 4 / 256, 256>>>(batch, weights);
    w2_kernel<<<MN_SZ / 8, 256>>>(weights);
    dim3 g(MN_SZ / BN, B_SZ / BM);     // (32, 32)
    gemm_mma_kernel<<<g, 256, SMEM_TOTAL>>>();
    output_kernel<<<B_SZ, 256>>>(out, batch, weights, decay, it);
}